// round 15
// baseline (speedup 1.0000x reference)
#include <cuda_runtime.h>
#include <cstdint>

#define NH 8
#define HD 48
#define CC 384
#define NN 1024
#define BB 16

// Scratch (device globals; no allocations allowed)
__device__ float g_q[BB*NH*NN*HD];
__device__ float g_k[BB*NH*NN*HD];
__device__ float g_v[BB*NH*NN*HD];
__device__ float g_o[BB*NN*CC];

// ---------------------------------------------------------------------------
// tf32 helpers (sm_80+ baseline ISA)
// ---------------------------------------------------------------------------
__device__ __forceinline__ float tf32r(float x) {
    uint32_t r;
    asm("cvt.rna.tf32.f32 %0, %1;" : "=r"(r) : "f"(x));
    return __uint_as_float(r);
}
__device__ __forceinline__ void mma_tf32(float* acc, const float* a, float b0, float b1) {
    asm volatile(
        "mma.sync.aligned.m16n8k8.row.col.f32.tf32.tf32.f32 "
        "{%0,%1,%2,%3}, {%4,%5,%6,%7}, {%8,%9}, {%0,%1,%2,%3};"
        : "+f"(acc[0]), "+f"(acc[1]), "+f"(acc[2]), "+f"(acc[3])
        : "r"(__float_as_uint(a[0])), "r"(__float_as_uint(a[1])),
          "r"(__float_as_uint(a[2])), "r"(__float_as_uint(a[3])),
          "r"(__float_as_uint(b0)),  "r"(__float_as_uint(b1)));
}
// pair-pack permutation: within each 8-block, (c, c+4) become adjacent
__device__ __forceinline__ int packc(int d) {
    return (d & ~7) + ((d & 3) << 1) + ((d >> 2) & 1);
}

// ===========================================================================
// GEMM 1 (tf32 TC, transpose-free): C[j][n] = sum_k w[j][k] * x[b][k][n]
// R10/R13 version (no register prefetch — it costs occupancy).
// ===========================================================================
__global__ __launch_bounds__(256) void gemm_qkv_tc(const float* __restrict__ x,
                                                   const float* __restrict__ w,
                                                   const float* __restrict__ bias) {
    __shared__ float As[128 * 36];   // [j][k]
    __shared__ float Bs[32 * 136];   // [k][n]
    const int b  = blockIdx.z;
    const int j0 = blockIdx.x * 128;
    const int n0 = blockIdx.y * 128;
    const int t  = threadIdx.x;
    const int w8 = t >> 5, lane = t & 31;
    const int lr = lane >> 2, lc = lane & 3;
    const int wm = w8 & 1, wn = w8 >> 1;

    float acc[4][4][4];
#pragma unroll
    for (int i = 0; i < 4; ++i)
#pragma unroll
        for (int j = 0; j < 4; ++j)
#pragma unroll
            for (int e = 0; e < 4; ++e) acc[i][j][e] = 0.f;

    const float* xb = x + (size_t)b * CC * NN;

    for (int k0 = 0; k0 < CC; k0 += 32) {
        __syncthreads();
#pragma unroll
        for (int r = 0; r < 4; ++r) {
            int idx = t + r * 256;
            int j = idx >> 3, k4 = idx & 7;
            float4 v = *(const float4*)(w + (size_t)(j0 + j) * CC + k0 + k4 * 4);
            v.x = tf32r(v.x); v.y = tf32r(v.y); v.z = tf32r(v.z); v.w = tf32r(v.w);
            *(float4*)&As[j * 36 + k4 * 4] = v;
        }
#pragma unroll
        for (int r = 0; r < 4; ++r) {
            int idx = t + r * 256;
            int kk = idx >> 5, m4 = idx & 31;
            float4 v = *(const float4*)(xb + (size_t)(k0 + kk) * NN + n0 + m4 * 4);
            v.x = tf32r(v.x); v.y = tf32r(v.y); v.z = tf32r(v.z); v.w = tf32r(v.w);
            *(float4*)&Bs[kk * 136 + m4 * 4] = v;
        }
        __syncthreads();
#pragma unroll
        for (int kb = 0; kb < 4; ++kb) {
            float af[4][4], bf[4][2];
#pragma unroll
            for (int mt = 0; mt < 4; ++mt) {
                int base = (wm * 64 + mt * 16 + lr) * 36 + kb * 8 + lc;
                af[mt][0] = As[base];
                af[mt][1] = As[base + 8 * 36];
                af[mt][2] = As[base + 4];
                af[mt][3] = As[base + 8 * 36 + 4];
            }
#pragma unroll
            for (int nb = 0; nb < 4; ++nb) {
                int nn = wn * 32 + nb * 8 + lr;
                bf[nb][0] = Bs[(kb * 8 + lc) * 136 + nn];
                bf[nb][1] = Bs[(kb * 8 + lc + 4) * 136 + nn];
            }
#pragma unroll
            for (int mt = 0; mt < 4; ++mt)
#pragma unroll
                for (int nb = 0; nb < 4; ++nb)
                    mma_tf32(acc[mt][nb], af[mt], bf[nb][0], bf[nb][1]);
        }
    }

    const int which = j0 / CC;
    float* dst = (which == 0) ? g_q : (which == 1) ? g_k : g_v;
#pragma unroll
    for (int mt = 0; mt < 4; ++mt) {
        int j1 = j0 + wm * 64 + mt * 16 + lr;
        int j2 = j1 + 8;
        int rem1 = j1 - which * CC;
        int h1 = rem1 / HD, d1 = rem1 - h1 * HD;
        int rem2 = j2 - which * CC;
        int h2 = rem2 / HD, d2 = rem2 - h2 * HD;
        float bj1 = bias[j1], bj2 = bias[j2];
        size_t base1 = ((size_t)b * NH + h1) * NN;
        size_t base2 = ((size_t)b * NH + h2) * NN;
#pragma unroll
        for (int nb = 0; nb < 4; ++nb) {
            int n = n0 + wn * 32 + nb * 8 + 2 * lc;
            dst[(base1 + n)     * HD + d1] = acc[mt][nb][0] + bj1;
            dst[(base1 + n + 1) * HD + d1] = acc[mt][nb][1] + bj1;
            dst[(base2 + n)     * HD + d2] = acc[mt][nb][2] + bj2;
            dst[(base2 + n + 1) * HD + d2] = acc[mt][nb][3] + bj2;
        }
    }
}

// ---------------------------------------------------------------------------
// Tensor-core flash attention, tf32 mma.sync, fused l2norm.
// R14: pair-packed Ks (S-phase B frags = 1 LDS.64) and pair-major Vp
// (PV B frags = 1 LDS.64); Q staging packed the same way (frag loads .64).
// K-norm shfl-reduce hoisted out of the store critical path.
// Math is bit-identical to R13 (only smem addresses changed).
// ---------------------------------------------------------------------------
#define KS_STRIDE 52
#define PS_STRIDE 68
#define VP_PITCH  100                       // pair-row: 48 d * 2 + 4 pad
#define SM_VS_F   (64 * KS_STRIDE)          // 3328
#define SM_PS_F   (SM_VS_F + 32 * VP_PITCH) // 3328 + 3200 = 6528
#define ATTN_SMEM_F (SM_PS_F + 8 * 16 * PS_STRIDE)

__global__ __launch_bounds__(256, 2) void attn_mma(const float* __restrict__ temp) {
    extern __shared__ float sm[];
    float* Ks = sm;
    float* Vp = sm + SM_VS_F;
    float* Ps = sm + SM_PS_F;

    const int t = threadIdx.x;
    const int w = t >> 5;
    const int lane = t & 31;
    const int lr = lane >> 2;
    const int lc = lane & 3;
    const int rql = t >> 2;      // row (0..63) for 4-threads-per-row loaders
    const int sq  = t & 3;       // quad slot; owns elements sq*12 .. sq*12+11
    const int i0 = blockIdx.x * 128;
    const int bh = blockIdx.y;
    const int h  = bh & (NH - 1);
    const float* qg = g_q + (size_t)bh * NN * HD;
    const float* kg = g_k + (size_t)bh * NN * HD;
    const float* vg = g_v + (size_t)bh * NN * HD;
    const float tpr = temp[h];
    const float mterm = fabsf(tpr);
    // V pair-major addressing constants for this thread (as loader)
    const int vpair = ((rql >> 3) << 2) + (rql & 3);   // 0..31
    const int vslot = (rql >> 2) & 1;
    const int vbase = vpair * VP_PITCH + vslot;

    // stage Q with fused l2norm, pair-packed, via the Ks/Vp region
#pragma unroll
    for (int it = 0; it < 2; ++it) {
        int r = it * 64 + rql;
        const float* qp = qg + (size_t)(i0 + r) * HD + sq * 12;
        float4 v0 = *(const float4*)(qp);
        float4 v1 = *(const float4*)(qp + 4);
        float4 v2 = *(const float4*)(qp + 8);
        float ss = v0.x*v0.x + v0.y*v0.y + v0.z*v0.z + v0.w*v0.w
                 + v1.x*v1.x + v1.y*v1.y + v1.z*v1.z + v1.w*v1.w
                 + v2.x*v2.x + v2.y*v2.y + v2.z*v2.z + v2.w*v2.w;
        ss += __shfl_xor_sync(0xffffffffu, ss, 1);
        ss += __shfl_xor_sync(0xffffffffu, ss, 2);
        float inv = 1.0f / fmaxf(sqrtf(ss), 1e-12f);
        float* d = &sm[r * KS_STRIDE];
        float vv[12] = {v0.x, v0.y, v0.z, v0.w, v1.x, v1.y, v1.z, v1.w,
                        v2.x, v2.y, v2.z, v2.w};
#pragma unroll
        for (int e = 0; e < 12; ++e)
            d[packc(sq * 12 + e)] = tf32r(vv[e] * inv);
    }
    __syncthreads();

    float qf[6][4];
    {
        const int mr = w * 16 + lr;
#pragma unroll
        for (int kb = 0; kb < 6; ++kb) {
            float2 q01 = *(float2*)&sm[mr * KS_STRIDE + kb * 8 + 2 * lc];
            float2 q23 = *(float2*)&sm[(mr + 8) * KS_STRIDE + kb * 8 + 2 * lc];
            qf[kb][0] = q01.x; qf[kb][2] = q01.y;
            qf[kb][1] = q23.x; qf[kb][3] = q23.y;
        }
    }

    float oacc[6][4];
#pragma unroll
    for (int i = 0; i < 6; ++i)
#pragma unroll
        for (int j = 0; j < 4; ++j) oacc[i][j] = 0.f;
    float rsum0 = 0.f, rsum1 = 0.f;
    float* Pw = Ps + w * 16 * PS_STRIDE;

    // prefetch tile 0 and compute its K-norm up front
    float4 kpre[3], vpre[3];
    float kinv;
    {
        const float* kp = kg + (size_t)rql * HD + sq * 12;
        const float* vp = vg + (size_t)rql * HD + sq * 12;
        kpre[0] = *(const float4*)(kp);     vpre[0] = *(const float4*)(vp);
        kpre[1] = *(const float4*)(kp + 4); vpre[1] = *(const float4*)(vp + 4);
        kpre[2] = *(const float4*)(kp + 8); vpre[2] = *(const float4*)(vp + 8);
        float ss = kpre[0].x*kpre[0].x + kpre[0].y*kpre[0].y + kpre[0].z*kpre[0].z + kpre[0].w*kpre[0].w
                 + kpre[1].x*kpre[1].x + kpre[1].y*kpre[1].y + kpre[1].z*kpre[1].z + kpre[1].w*kpre[1].w
                 + kpre[2].x*kpre[2].x + kpre[2].y*kpre[2].y + kpre[2].z*kpre[2].z + kpre[2].w*kpre[2].w;
        ss += __shfl_xor_sync(0xffffffffu, ss, 1);
        ss += __shfl_xor_sync(0xffffffffu, ss, 2);
        kinv = 1.0f / fmaxf(sqrtf(ss), 1e-12f);
    }

    for (int kt = 0; kt < 16; ++kt) {
        __syncthreads();   // prior compute done
        // store K (normalized, pair-packed) and V (pair-major), tf32-rounded
        {
            float kv[12] = {kpre[0].x, kpre[0].y, kpre[0].z, kpre[0].w,
                            kpre[1].x, kpre[1].y, kpre[1].z, kpre[1].w,
                            kpre[2].x, kpre[2].y, kpre[2].z, kpre[2].w};
            float vv[12] = {vpre[0].x, vpre[0].y, vpre[0].z, vpre[0].w,
                            vpre[1].x, vpre[1].y, vpre[1].z, vpre[1].w,
                            vpre[2].x, vpre[2].y, vpre[2].z, vpre[2].w};
            float* dk = &Ks[rql * KS_STRIDE];
            float* dv = &Vp[vbase + 2 * (sq * 12)];
#pragma unroll
            for (int e = 0; e < 12; ++e) {
                dk[packc(sq * 12 + e)] = tf32r(kv[e] * kinv);
                dv[2 * e] = tf32r(vv[e]);
            }
        }
        // issue next tile's loads; they complete under the mma phase
        if (kt < 15) {
            const int k1 = (kt + 1) * 64;
            const float* kp = kg + (size_t)(k1 + rql) * HD + sq * 12;
            const float* vp = vg + (size_t)(k1 + rql) * HD + sq * 12;
            kpre[0] = *(const float4*)(kp);     vpre[0] = *(const float4*)(vp);
            kpre[1] = *(const float4*)(kp + 4); vpre[1] = *(const float4*)(vp + 4);
            kpre[2] = *(const float4*)(kp + 8); vpre[2] = *(const float4*)(vp + 8);
        }
        __syncthreads();

        // ---- S = Q.K^T + softmax, two halves of 4 n-blocks ----
#pragma unroll
        for (int half = 0; half < 2; ++half) {
            float sacc[4][4];
#pragma unroll
            for (int i = 0; i < 4; ++i)
#pragma unroll
                for (int j = 0; j < 4; ++j) sacc[i][j] = 0.f;
#pragma unroll
            for (int nb4 = 0; nb4 < 4; ++nb4) {
                const int nb = half * 4 + nb4;
                const float* kbase = Ks + (nb * 8 + lr) * KS_STRIDE + 2 * lc;
#pragma unroll
                for (int kb = 0; kb < 6; ++kb) {
                    float2 bb = *(const float2*)(kbase + kb * 8);
                    mma_tf32(sacc[nb4], qf[kb], bb.x, bb.y);
                }
            }
#pragma unroll
            for (int nb4 = 0; nb4 < 4; ++nb4) {
                const int nb = half * 4 + nb4;
                float p0 = __expf(fmaf(sacc[nb4][0], tpr, -mterm));
                float p1 = __expf(fmaf(sacc[nb4][1], tpr, -mterm));
                float p2 = __expf(fmaf(sacc[nb4][2], tpr, -mterm));
                float p3 = __expf(fmaf(sacc[nb4][3], tpr, -mterm));
                rsum0 += p0 + p1;
                rsum1 += p2 + p3;
                *(float2*)&Pw[lr * PS_STRIDE + nb * 8 + 2 * lc] =
                    make_float2(tf32r(p0), tf32r(p1));
                *(float2*)&Pw[(lr + 8) * PS_STRIDE + nb * 8 + 2 * lc] =
                    make_float2(tf32r(p2), tf32r(p3));
            }
        }
        __syncwarp();

        // ---- O += P.V  (V B-frags are single LDS.64 from pair-major Vp) ----
#pragma unroll
        for (int kb2 = 0; kb2 < 8; ++kb2) {
            float af[4];
            af[0] = Pw[lr * PS_STRIDE + kb2 * 8 + lc];
            af[1] = Pw[(lr + 8) * PS_STRIDE + kb2 * 8 + lc];
            af[2] = Pw[lr * PS_STRIDE + kb2 * 8 + lc + 4];
            af[3] = Pw[(lr + 8) * PS_STRIDE + kb2 * 8 + lc + 4];
            const float* vrow = Vp + (kb2 * 4 + lc) * VP_PITCH + 2 * lr;
#pragma unroll
            for (int nb2 = 0; nb2 < 6; ++nb2) {
                float2 bb = *(const float2*)(vrow + 16 * nb2);
                mma_tf32(oacc[nb2], af, bb.x, bb.y);
            }
        }

        // compute next tile's K norm from the just-prefetched registers
        if (kt < 15) {
            float ss = kpre[0].x*kpre[0].x + kpre[0].y*kpre[0].y + kpre[0].z*kpre[0].z + kpre[0].w*kpre[0].w
                     + kpre[1].x*kpre[1].x + kpre[1].y*kpre[1].y + kpre[1].z*kpre[1].z + kpre[1].w*kpre[1].w
                     + kpre[2].x*kpre[2].x + kpre[2].y*kpre[2].y + kpre[2].z*kpre[2].z + kpre[2].w*kpre[2].w;
            ss += __shfl_xor_sync(0xffffffffu, ss, 1);
            ss += __shfl_xor_sync(0xffffffffu, ss, 2);
            kinv = 1.0f / fmaxf(sqrtf(ss), 1e-12f);
        }
    }

    rsum0 += __shfl_xor_sync(0xffffffffu, rsum0, 1);
    rsum0 += __shfl_xor_sync(0xffffffffu, rsum0, 2);
    rsum1 += __shfl_xor_sync(0xffffffffu, rsum1, 1);
    rsum1 += __shfl_xor_sync(0xffffffffu, rsum1, 2);
    const float inv0 = 1.0f / rsum0;
    const float inv1 = 1.0f / rsum1;
    const int b = bh >> 3;
    const int row0 = i0 + w * 16 + lr;
    float* o0 = g_o + ((size_t)b * NN + row0) * CC + h * HD;
    float* o1 = o0 + 8 * CC;
#pragma unroll
    for (int nb = 0; nb < 6; ++nb) {
        *(float2*)&o0[nb * 8 + 2 * lc] = make_float2(oacc[nb][0] * inv0, oacc[nb][1] * inv0);
        *(float2*)&o1[nb * 8 + 2 * lc] = make_float2(oacc[nb][2] * inv1, oacc[nb][3] * inv1);
    }
}

// ===========================================================================
// GEMM 2 (tf32 TC): out[b,j,n] = sum_c g_o[b,n,c]*proj_w[j,c]+pb[j]
// R12/R13 version: 128x128 tile, register prefetch, (256,2).
// ===========================================================================
__global__ __launch_bounds__(256, 2) void gemm_proj_tc(const float* __restrict__ w,
                                                       const float* __restrict__ bias,
                                                       float* __restrict__ out) {
    __shared__ float Sm[9216];
    float* As = Sm;               // [m][k] 128x36
    float* Bs = Sm + 128 * 36;    // [j][k] 128x36
    float* Cs = Sm;               // [j][m] 64x132 per pass

    const int b  = blockIdx.z;
    const int m0 = blockIdx.y * 128;
    const int j0 = blockIdx.x * 128;
    const int t  = threadIdx.x;
    const int w8 = t >> 5, lane = t & 31;
    const int lr = lane >> 2, lc = lane & 3;
    const int wm = w8 & 1, wn = w8 >> 1;

    float acc[4][4][4];
#pragma unroll
    for (int i = 0; i < 4; ++i)
#pragma unroll
        for (int j = 0; j < 4; ++j)
#pragma unroll
            for (int e = 0; e < 4; ++e) acc[i][j][e] = 0.f;

    const float* A = g_o + (size_t)b * NN * CC;

    float4 apre[4], bpre[4];
#pragma unroll
    for (int r = 0; r < 4; ++r) {
        int idx = t + r * 256;
        int m = idx >> 3, k4 = idx & 7;
        apre[r] = *(const float4*)(A + (size_t)(m0 + m) * CC + k4 * 4);
        bpre[r] = *(const float4*)(w + (size_t)(j0 + m) * CC + k4 * 4);
    }

    for (int k0 = 0; k0 < CC; k0 += 32) {
        __syncthreads();
#pragma unroll
        for (int r = 0; r < 4; ++r) {
            int idx = t + r * 256;
            int m = idx >> 3, k4 = idx & 7;
            float4 v = apre[r];
            v.x = tf32r(v.x); v.y = tf32r(v.y); v.z = tf32r(v.z); v.w = tf32r(v.w);
            *(float4*)&As[m * 36 + k4 * 4] = v;
            float4 u = bpre[r];
            u.x = tf32r(u.x); u.y = tf32r(u.y); u.z = tf32r(u.z); u.w = tf32r(u.w);
            *(float4*)&Bs[m * 36 + k4 * 4] = u;
        }
        if (k0 + 32 < CC) {
            const int k1 = k0 + 32;
#pragma unroll
            for (int r = 0; r < 4; ++r) {
                int idx = t + r * 256;
                int m = idx >> 3, k4 = idx & 7;
                apre[r] = *(const float4*)(A + (size_t)(m0 + m) * CC + k1 + k4 * 4);
                bpre[r] = *(const float4*)(w + (size_t)(j0 + m) * CC + k1 + k4 * 4);
            }
        }
        __syncthreads();
#pragma unroll
        for (int kb = 0; kb < 4; ++kb) {
            float af[4][4], bf[4][2];
#pragma unroll
            for (int mt = 0; mt < 4; ++mt) {
                int base = (wm * 64 + mt * 16 + lr) * 36 + kb * 8 + lc;
                af[mt][0] = As[base];
                af[mt][1] = As[base + 8 * 36];
                af[mt][2] = As[base + 4];
                af[mt][3] = As[base + 8 * 36 + 4];
            }
#pragma unroll
            for (int nb = 0; nb < 4; ++nb) {
                int bb = (wn * 32 + nb * 8 + lr) * 36 + kb * 8 + lc;
                bf[nb][0] = Bs[bb];
                bf[nb][1] = Bs[bb + 4];
            }
#pragma unroll
            for (int mt = 0; mt < 4; ++mt)
#pragma unroll
                for (int nb = 0; nb < 4; ++nb)
                    mma_tf32(acc[mt][nb], af[mt], bf[nb][0], bf[nb][1]);
        }
    }

    // 2-pass epilogue: stage C[j][m] -> coalesced store along n
#pragma unroll
    for (int hh = 0; hh < 2; ++hh) {
        __syncthreads();
        if ((wn >> 1) == hh) {
#pragma unroll
            for (int mt = 0; mt < 4; ++mt) {
                int m1 = wm * 64 + mt * 16 + lr;
                int m2 = m1 + 8;
#pragma unroll
                for (int nb = 0; nb < 4; ++nb) {
                    int jl = (wn & 1) * 32 + nb * 8 + 2 * lc;
                    Cs[jl * 132 + m1]       = acc[mt][nb][0];
                    Cs[(jl + 1) * 132 + m1] = acc[mt][nb][1];
                    Cs[jl * 132 + m2]       = acc[mt][nb][2];
                    Cs[(jl + 1) * 132 + m2] = acc[mt][nb][3];
                }
            }
        }
        __syncthreads();
#pragma unroll
        for (int r = 0; r < 8; ++r) {
            int idx = t + r * 256;
            int jl = idx >> 5, m4 = idx & 31;
            int jg = j0 + hh * 64 + jl;
            float bj = bias[jg];
            float4 v = *(float4*)&Cs[jl * 132 + m4 * 4];
            v.x += bj; v.y += bj; v.z += bj; v.w += bj;
            *(float4*)(out + ((size_t)b * CC + jg) * NN + m0 + m4 * 4) = v;
        }
    }
}

// ===========================================================================
extern "C" void kernel_launch(void* const* d_in, const int* in_sizes, int n_in,
                              void* d_out, int out_size) {
    const float* x      = (const float*)d_in[0];
    const float* temp   = (const float*)d_in[1];
    const float* qkv_w  = (const float*)d_in[2];
    const float* qkv_b  = (const float*)d_in[3];
    const float* proj_w = (const float*)d_in[4];
    const float* proj_b = (const float*)d_in[5];
    float* out = (float*)d_out;

    static const int ATTN_SMEM = ATTN_SMEM_F * 4;
    cudaFuncSetAttribute(attn_mma, cudaFuncAttributeMaxDynamicSharedMemorySize,
                         ATTN_SMEM);

    gemm_qkv_tc<<<dim3(9, 8, BB), 256>>>(x, qkv_w, qkv_b);
    attn_mma<<<dim3(8, BB * NH), 256, ATTN_SMEM>>>(temp);
    gemm_proj_tc<<<dim3(3, 8, BB), 256>>>(proj_w, proj_b, out);
}

// round 16
// speedup vs baseline: 1.2108x; 1.2108x over previous
#include <cuda_runtime.h>
#include <cstdint>

#define NH 8
#define HD 48
#define CC 384
#define NN 1024
#define BB 16

// Scratch (device globals; no allocations allowed)
__device__ float g_q[BB*NH*NN*HD];
__device__ float g_k[BB*NH*NN*HD];
__device__ float g_v[BB*NH*NN*HD];
__device__ float g_o[BB*NN*CC];

// ---------------------------------------------------------------------------
// tf32 helpers (sm_80+ baseline ISA)
// ---------------------------------------------------------------------------
__device__ __forceinline__ float tf32r(float x) {
    uint32_t r;
    asm("cvt.rna.tf32.f32 %0, %1;" : "=r"(r) : "f"(x));
    return __uint_as_float(r);
}
__device__ __forceinline__ void mma_tf32(float* acc, const float* a, float b0, float b1) {
    asm volatile(
        "mma.sync.aligned.m16n8k8.row.col.f32.tf32.tf32.f32 "
        "{%0,%1,%2,%3}, {%4,%5,%6,%7}, {%8,%9}, {%0,%1,%2,%3};"
        : "+f"(acc[0]), "+f"(acc[1]), "+f"(acc[2]), "+f"(acc[3])
        : "r"(__float_as_uint(a[0])), "r"(__float_as_uint(a[1])),
          "r"(__float_as_uint(a[2])), "r"(__float_as_uint(a[3])),
          "r"(__float_as_uint(b0)),  "r"(__float_as_uint(b1)));
}

// ===========================================================================
// GEMM 1 (tf32 TC, transpose-free): C[j][n] = sum_k w[j][k] * x[b][k][n]
// R10 version — measured 106us. No prefetch (costs occupancy).
// ===========================================================================
__global__ __launch_bounds__(256) void gemm_qkv_tc(const float* __restrict__ x,
                                                   const float* __restrict__ w,
                                                   const float* __restrict__ bias) {
    __shared__ float As[128 * 36];   // [j][k]
    __shared__ float Bs[32 * 136];   // [k][n]
    const int b  = blockIdx.z;
    const int j0 = blockIdx.x * 128;
    const int n0 = blockIdx.y * 128;
    const int t  = threadIdx.x;
    const int w8 = t >> 5, lane = t & 31;
    const int lr = lane >> 2, lc = lane & 3;
    const int wm = w8 & 1, wn = w8 >> 1;

    float acc[4][4][4];
#pragma unroll
    for (int i = 0; i < 4; ++i)
#pragma unroll
        for (int j = 0; j < 4; ++j)
#pragma unroll
            for (int e = 0; e < 4; ++e) acc[i][j][e] = 0.f;

    const float* xb = x + (size_t)b * CC * NN;

    for (int k0 = 0; k0 < CC; k0 += 32) {
        __syncthreads();
#pragma unroll
        for (int r = 0; r < 4; ++r) {
            int idx = t + r * 256;
            int j = idx >> 3, k4 = idx & 7;
            float4 v = *(const float4*)(w + (size_t)(j0 + j) * CC + k0 + k4 * 4);
            v.x = tf32r(v.x); v.y = tf32r(v.y); v.z = tf32r(v.z); v.w = tf32r(v.w);
            *(float4*)&As[j * 36 + k4 * 4] = v;
        }
#pragma unroll
        for (int r = 0; r < 4; ++r) {
            int idx = t + r * 256;
            int kk = idx >> 5, m4 = idx & 31;
            float4 v = *(const float4*)(xb + (size_t)(k0 + kk) * NN + n0 + m4 * 4);
            v.x = tf32r(v.x); v.y = tf32r(v.y); v.z = tf32r(v.z); v.w = tf32r(v.w);
            *(float4*)&Bs[kk * 136 + m4 * 4] = v;
        }
        __syncthreads();
#pragma unroll
        for (int kb = 0; kb < 4; ++kb) {
            float af[4][4], bf[4][2];
#pragma unroll
            for (int mt = 0; mt < 4; ++mt) {
                int base = (wm * 64 + mt * 16 + lr) * 36 + kb * 8 + lc;
                af[mt][0] = As[base];
                af[mt][1] = As[base + 8 * 36];
                af[mt][2] = As[base + 4];
                af[mt][3] = As[base + 8 * 36 + 4];
            }
#pragma unroll
            for (int nb = 0; nb < 4; ++nb) {
                int nn = wn * 32 + nb * 8 + lr;
                bf[nb][0] = Bs[(kb * 8 + lc) * 136 + nn];
                bf[nb][1] = Bs[(kb * 8 + lc + 4) * 136 + nn];
            }
#pragma unroll
            for (int mt = 0; mt < 4; ++mt)
#pragma unroll
                for (int nb = 0; nb < 4; ++nb)
                    mma_tf32(acc[mt][nb], af[mt], bf[nb][0], bf[nb][1]);
        }
    }

    const int which = j0 / CC;
    float* dst = (which == 0) ? g_q : (which == 1) ? g_k : g_v;
#pragma unroll
    for (int mt = 0; mt < 4; ++mt) {
        int j1 = j0 + wm * 64 + mt * 16 + lr;
        int j2 = j1 + 8;
        int rem1 = j1 - which * CC;
        int h1 = rem1 / HD, d1 = rem1 - h1 * HD;
        int rem2 = j2 - which * CC;
        int h2 = rem2 / HD, d2 = rem2 - h2 * HD;
        float bj1 = bias[j1], bj2 = bias[j2];
        size_t base1 = ((size_t)b * NH + h1) * NN;
        size_t base2 = ((size_t)b * NH + h2) * NN;
#pragma unroll
        for (int nb = 0; nb < 4; ++nb) {
            int n = n0 + wn * 32 + nb * 8 + 2 * lc;
            dst[(base1 + n)     * HD + d1] = acc[mt][nb][0] + bj1;
            dst[(base1 + n + 1) * HD + d1] = acc[mt][nb][1] + bj1;
            dst[(base2 + n)     * HD + d2] = acc[mt][nb][2] + bj2;
            dst[(base2 + n + 1) * HD + d2] = acc[mt][nb][3] + bj2;
        }
    }
}

// ---------------------------------------------------------------------------
// L2-normalize rows of g_q and g_k. R16: 4 threads/row, float4 loads/stores,
// fully coalesced (thread t touches floats t*12 .. t*12+11 of its block's
// contiguous 64-row span). 2-shfl quad reduce.
// ---------------------------------------------------------------------------
__global__ __launch_bounds__(256) void l2norm_kernel() {
    const int rb = blockIdx.x;               // 4096 blocks; 2048 per tensor
    float* base = (rb < 2048) ? g_q : g_k;
    const int t = threadIdx.x;
    const int row = (rb & 2047) * 64 + (t >> 2);
    const int sq = t & 3;
    float* p = base + (size_t)row * HD + sq * 12;
    float4 v0 = *(const float4*)(p);
    float4 v1 = *(const float4*)(p + 4);
    float4 v2 = *(const float4*)(p + 8);
    float ss = v0.x*v0.x + v0.y*v0.y + v0.z*v0.z + v0.w*v0.w
             + v1.x*v1.x + v1.y*v1.y + v1.z*v1.z + v1.w*v1.w
             + v2.x*v2.x + v2.y*v2.y + v2.z*v2.z + v2.w*v2.w;
    ss += __shfl_xor_sync(0xffffffffu, ss, 1);
    ss += __shfl_xor_sync(0xffffffffu, ss, 2);
    float inv = 1.0f / fmaxf(sqrtf(ss), 1e-12f);
    v0.x *= inv; v0.y *= inv; v0.z *= inv; v0.w *= inv;
    v1.x *= inv; v1.y *= inv; v1.z *= inv; v1.w *= inv;
    v2.x *= inv; v2.y *= inv; v2.z *= inv; v2.w *= inv;
    *(float4*)(p)     = v0;
    *(float4*)(p + 4) = v1;
    *(float4*)(p + 8) = v2;
}

// ---------------------------------------------------------------------------
// Tensor-core flash attention, tf32 mma.sync — EXACT R11 version (190us):
// register prefetch of next K/V tile + 2 CTAs/SM, S accum in two halves.
// ---------------------------------------------------------------------------
#define KS_STRIDE 52
#define VS_STRIDE 72
#define PS_STRIDE 68
#define SM_VS_F   (64 * KS_STRIDE)
#define SM_PS_F   (SM_VS_F + 64 * VS_STRIDE)
#define ATTN_SMEM_F (SM_PS_F + 8 * 16 * PS_STRIDE)

__global__ __launch_bounds__(256, 2) void attn_mma(const float* __restrict__ temp) {
    extern __shared__ float sm[];
    float* Ks = sm;
    float* Vs = sm + SM_VS_F;
    float* Ps = sm + SM_PS_F;

    const int t = threadIdx.x;
    const int w = t >> 5;
    const int lane = t & 31;
    const int lr = lane >> 2;
    const int lc = lane & 3;
    const int i0 = blockIdx.x * 128;
    const int bh = blockIdx.y;
    const int h  = bh & (NH - 1);
    const float* qg = g_q + (size_t)bh * NN * HD;
    const float* kg = g_k + (size_t)bh * NN * HD;
    const float* vg = g_v + (size_t)bh * NN * HD;
    const float tpr = temp[h];
    const float mterm = fabsf(tpr);

    // stage Q via Ks region, extract persistent fragments
    for (int idx = t; idx < 128 * 12; idx += 256) {
        int r = idx / 12, c4 = idx % 12;
        float4 v = *(const float4*)(qg + (size_t)(i0 + r) * HD + c4 * 4);
        v.x = tf32r(v.x); v.y = tf32r(v.y); v.z = tf32r(v.z); v.w = tf32r(v.w);
        *(float4*)&sm[r * KS_STRIDE + c4 * 4] = v;
    }
    __syncthreads();

    float qf[6][4];
    {
        const int mr = w * 16 + lr;
#pragma unroll
        for (int kb = 0; kb < 6; ++kb) {
            qf[kb][0] = sm[mr * KS_STRIDE + kb * 8 + lc];
            qf[kb][1] = sm[(mr + 8) * KS_STRIDE + kb * 8 + lc];
            qf[kb][2] = sm[mr * KS_STRIDE + kb * 8 + lc + 4];
            qf[kb][3] = sm[(mr + 8) * KS_STRIDE + kb * 8 + lc + 4];
        }
    }

    float oacc[6][4];
#pragma unroll
    for (int i = 0; i < 6; ++i)
#pragma unroll
        for (int j = 0; j < 4; ++j) oacc[i][j] = 0.f;
    float rsum0 = 0.f, rsum1 = 0.f;
    float* Pw = Ps + w * 16 * PS_STRIDE;

    // prefetch tile 0 into registers
    float4 kpre[3], vpre[3];
#pragma unroll
    for (int r = 0; r < 3; ++r) {
        int idx = t + r * 256;
        int n = idx / 12, c4 = idx % 12;
        kpre[r] = *(const float4*)(kg + (size_t)n * HD + c4 * 4);
        vpre[r] = *(const float4*)(vg + (size_t)n * HD + c4 * 4);
    }

    for (int kt = 0; kt < 16; ++kt) {
        __syncthreads();   // prior compute done
        // store prefetched tile to smem (tf32-rounded)
#pragma unroll
        for (int r = 0; r < 3; ++r) {
            int idx = t + r * 256;
            int n = idx / 12, c4 = idx % 12;
            float4 v = kpre[r];
            v.x = tf32r(v.x); v.y = tf32r(v.y); v.z = tf32r(v.z); v.w = tf32r(v.w);
            *(float4*)&Ks[n * KS_STRIDE + c4 * 4] = v;
            float4 u = vpre[r];
            u.x = tf32r(u.x); u.y = tf32r(u.y); u.z = tf32r(u.z); u.w = tf32r(u.w);
            *(float4*)&Vs[n * VS_STRIDE + c4 * 4] = u;
        }
        // issue next tile's loads; they complete under the mma phase
        if (kt < 15) {
            const int k1 = (kt + 1) * 64;
#pragma unroll
            for (int r = 0; r < 3; ++r) {
                int idx = t + r * 256;
                int n = idx / 12, c4 = idx % 12;
                kpre[r] = *(const float4*)(kg + (size_t)(k1 + n) * HD + c4 * 4);
                vpre[r] = *(const float4*)(vg + (size_t)(k1 + n) * HD + c4 * 4);
            }
        }
        __syncthreads();

        // ---- S = Q.K^T + softmax, two halves of 4 n-blocks ----
#pragma unroll
        for (int half = 0; half < 2; ++half) {
            float sacc[4][4];
#pragma unroll
            for (int i = 0; i < 4; ++i)
#pragma unroll
                for (int j = 0; j < 4; ++j) sacc[i][j] = 0.f;
#pragma unroll
            for (int nb4 = 0; nb4 < 4; ++nb4) {
                const int nb = half * 4 + nb4;
                const float* kbase = Ks + (nb * 8 + lr) * KS_STRIDE + lc;
#pragma unroll
                for (int kb = 0; kb < 6; ++kb) {
                    float b0 = kbase[kb * 8];
                    float b1 = kbase[kb * 8 + 4];
                    mma_tf32(sacc[nb4], qf[kb], b0, b1);
                }
            }
#pragma unroll
            for (int nb4 = 0; nb4 < 4; ++nb4) {
                const int nb = half * 4 + nb4;
                float p0 = __expf(fmaf(sacc[nb4][0], tpr, -mterm));
                float p1 = __expf(fmaf(sacc[nb4][1], tpr, -mterm));
                float p2 = __expf(fmaf(sacc[nb4][2], tpr, -mterm));
                float p3 = __expf(fmaf(sacc[nb4][3], tpr, -mterm));
                rsum0 += p0 + p1;
                rsum1 += p2 + p3;
                *(float2*)&Pw[lr * PS_STRIDE + nb * 8 + 2 * lc] =
                    make_float2(tf32r(p0), tf32r(p1));
                *(float2*)&Pw[(lr + 8) * PS_STRIDE + nb * 8 + 2 * lc] =
                    make_float2(tf32r(p2), tf32r(p3));
            }
        }
        __syncwarp();

        // ---- O += P.V ----
#pragma unroll
        for (int kb2 = 0; kb2 < 8; ++kb2) {
            float af[4];
            af[0] = Pw[lr * PS_STRIDE + kb2 * 8 + lc];
            af[1] = Pw[(lr + 8) * PS_STRIDE + kb2 * 8 + lc];
            af[2] = Pw[lr * PS_STRIDE + kb2 * 8 + lc + 4];
            af[3] = Pw[(lr + 8) * PS_STRIDE + kb2 * 8 + lc + 4];
            const float* vb0 = Vs + (kb2 * 8 + lc) * VS_STRIDE + lr;
            const float* vb1 = Vs + (kb2 * 8 + lc + 4) * VS_STRIDE + lr;
#pragma unroll
            for (int nb2 = 0; nb2 < 6; ++nb2) {
                mma_tf32(oacc[nb2], af, vb0[nb2 * 8], vb1[nb2 * 8]);
            }
        }
    }

    rsum0 += __shfl_xor_sync(0xffffffffu, rsum0, 1);
    rsum0 += __shfl_xor_sync(0xffffffffu, rsum0, 2);
    rsum1 += __shfl_xor_sync(0xffffffffu, rsum1, 1);
    rsum1 += __shfl_xor_sync(0xffffffffu, rsum1, 2);
    const float inv0 = 1.0f / rsum0;
    const float inv1 = 1.0f / rsum1;
    const int b = bh >> 3;
    const int row0 = i0 + w * 16 + lr;
    float* o0 = g_o + ((size_t)b * NN + row0) * CC + h * HD;
    float* o1 = o0 + 8 * CC;
#pragma unroll
    for (int nb = 0; nb < 6; ++nb) {
        *(float2*)&o0[nb * 8 + 2 * lc] = make_float2(oacc[nb][0] * inv0, oacc[nb][1] * inv0);
        *(float2*)&o1[nb * 8 + 2 * lc] = make_float2(oacc[nb][2] * inv1, oacc[nb][3] * inv1);
    }
}

// ===========================================================================
// GEMM 2 (tf32 TC): out[b,j,n] = sum_c g_o[b,n,c]*proj_w[j,c]+pb[j]
// R12 version (43us): 128x128 tile, register prefetch, (256,2).
// ===========================================================================
__global__ __launch_bounds__(256, 2) void gemm_proj_tc(const float* __restrict__ w,
                                                       const float* __restrict__ bias,
                                                       float* __restrict__ out) {
    __shared__ float Sm[9216];
    float* As = Sm;               // [m][k] 128x36
    float* Bs = Sm + 128 * 36;    // [j][k] 128x36
    float* Cs = Sm;               // [j][m] 64x132 per pass

    const int b  = blockIdx.z;
    const int m0 = blockIdx.y * 128;
    const int j0 = blockIdx.x * 128;
    const int t  = threadIdx.x;
    const int w8 = t >> 5, lane = t & 31;
    const int lr = lane >> 2, lc = lane & 3;
    const int wm = w8 & 1, wn = w8 >> 1;

    float acc[4][4][4];
#pragma unroll
    for (int i = 0; i < 4; ++i)
#pragma unroll
        for (int j = 0; j < 4; ++j)
#pragma unroll
            for (int e = 0; e < 4; ++e) acc[i][j][e] = 0.f;

    const float* A = g_o + (size_t)b * NN * CC;

    float4 apre[4], bpre[4];
#pragma unroll
    for (int r = 0; r < 4; ++r) {
        int idx = t + r * 256;
        int m = idx >> 3, k4 = idx & 7;
        apre[r] = *(const float4*)(A + (size_t)(m0 + m) * CC + k4 * 4);
        bpre[r] = *(const float4*)(w + (size_t)(j0 + m) * CC + k4 * 4);
    }

    for (int k0 = 0; k0 < CC; k0 += 32) {
        __syncthreads();
#pragma unroll
        for (int r = 0; r < 4; ++r) {
            int idx = t + r * 256;
            int m = idx >> 3, k4 = idx & 7;
            float4 v = apre[r];
            v.x = tf32r(v.x); v.y = tf32r(v.y); v.z = tf32r(v.z); v.w = tf32r(v.w);
            *(float4*)&As[m * 36 + k4 * 4] = v;
            float4 u = bpre[r];
            u.x = tf32r(u.x); u.y = tf32r(u.y); u.z = tf32r(u.z); u.w = tf32r(u.w);
            *(float4*)&Bs[m * 36 + k4 * 4] = u;
        }
        if (k0 + 32 < CC) {
            const int k1 = k0 + 32;
#pragma unroll
            for (int r = 0; r < 4; ++r) {
                int idx = t + r * 256;
                int m = idx >> 3, k4 = idx & 7;
                apre[r] = *(const float4*)(A + (size_t)(m0 + m) * CC + k1 + k4 * 4);
                bpre[r] = *(const float4*)(w + (size_t)(j0 + m) * CC + k1 + k4 * 4);
            }
        }
        __syncthreads();
#pragma unroll
        for (int kb = 0; kb < 4; ++kb) {
            float af[4][4], bf[4][2];
#pragma unroll
            for (int mt = 0; mt < 4; ++mt) {
                int base = (wm * 64 + mt * 16 + lr) * 36 + kb * 8 + lc;
                af[mt][0] = As[base];
                af[mt][1] = As[base + 8 * 36];
                af[mt][2] = As[base + 4];
                af[mt][3] = As[base + 8 * 36 + 4];
            }
#pragma unroll
            for (int nb = 0; nb < 4; ++nb) {
                int bb = (wn * 32 + nb * 8 + lr) * 36 + kb * 8 + lc;
                bf[nb][0] = Bs[bb];
                bf[nb][1] = Bs[bb + 4];
            }
#pragma unroll
            for (int mt = 0; mt < 4; ++mt)
#pragma unroll
                for (int nb = 0; nb < 4; ++nb)
                    mma_tf32(acc[mt][nb], af[mt], bf[nb][0], bf[nb][1]);
        }
    }

    // 2-pass epilogue: stage C[j][m] -> coalesced store along n
#pragma unroll
    for (int hh = 0; hh < 2; ++hh) {
        __syncthreads();
        if ((wn >> 1) == hh) {
#pragma unroll
            for (int mt = 0; mt < 4; ++mt) {
                int m1 = wm * 64 + mt * 16 + lr;
                int m2 = m1 + 8;
#pragma unroll
                for (int nb = 0; nb < 4; ++nb) {
                    int jl = (wn & 1) * 32 + nb * 8 + 2 * lc;
                    Cs[jl * 132 + m1]       = acc[mt][nb][0];
                    Cs[(jl + 1) * 132 + m1] = acc[mt][nb][1];
                    Cs[jl * 132 + m2]       = acc[mt][nb][2];
                    Cs[(jl + 1) * 132 + m2] = acc[mt][nb][3];
                }
            }
        }
        __syncthreads();
#pragma unroll
        for (int r = 0; r < 8; ++r) {
            int idx = t + r * 256;
            int jl = idx >> 5, m4 = idx & 31;
            int jg = j0 + hh * 64 + jl;
            float bj = bias[jg];
            float4 v = *(float4*)&Cs[jl * 132 + m4 * 4];
            v.x += bj; v.y += bj; v.z += bj; v.w += bj;
            *(float4*)(out + ((size_t)b * CC + jg) * NN + m0 + m4 * 4) = v;
        }
    }
}

// ===========================================================================
extern "C" void kernel_launch(void* const* d_in, const int* in_sizes, int n_in,
                              void* d_out, int out_size) {
    const float* x      = (const float*)d_in[0];
    const float* temp   = (const float*)d_in[1];
    const float* qkv_w  = (const float*)d_in[2];
    const float* qkv_b  = (const float*)d_in[3];
    const float* proj_w = (const float*)d_in[4];
    const float* proj_b = (const float*)d_in[5];
    float* out = (float*)d_out;

    static const int ATTN_SMEM = ATTN_SMEM_F * 4;   // 66560 bytes
    cudaFuncSetAttribute(attn_mma, cudaFuncAttributeMaxDynamicSharedMemorySize,
                         ATTN_SMEM);

    gemm_qkv_tc<<<dim3(9, 8, BB), 256>>>(x, qkv_w, qkv_b);
    l2norm_kernel<<<4096, 256>>>();
    attn_mma<<<dim3(8, BB * NH), 256, ATTN_SMEM>>>(temp);
    gemm_proj_tc<<<dim3(3, 8, BB), 256>>>(proj_w, proj_b, out);
}